// round 1
// baseline (speedup 1.0000x reference)
#include <cuda_runtime.h>
#include <cuda_bf16.h>
#include <cstdint>

// Problem constants (from reference: C=32,H=32,W=32,KS=3, B=32)
constexpr int NDIM = 32 * 32 * 32 + 1;   // 32769
constexpr int KDIM = 32 * 3 * 3;         // 288
constexpr int BDIM = 32;

// Scratch: x transposed to [N, B] so a warp-gather of one column index is a
// single contiguous 128B line. (__device__ global: allocation-guard safe.)
__device__ float g_xT[(size_t)NDIM * BDIM];

// ---------------------------------------------------------------------------
// Kernel 1: transpose x [B, N] -> x_T [N, B], smem-tiled, fully coalesced.
// ---------------------------------------------------------------------------
__global__ __launch_bounds__(1024) void transpose_kernel(const float* __restrict__ x)
{
    __shared__ float tile[32][33];
    const int n0 = blockIdx.x * 32;
    const int tx = threadIdx.x;  // n offset on load, b on store
    const int ty = threadIdx.y;  // b on load, n offset on store

    const int n_load = n0 + tx;
    if (n_load < NDIM)
        tile[ty][tx] = x[(size_t)ty * NDIM + n_load];
    __syncthreads();

    const int n_store = n0 + ty;
    if (n_store < NDIM)
        g_xT[(size_t)n_store * BDIM + tx] = tile[tx][ty];
}

// ---------------------------------------------------------------------------
// Kernel 2: one warp per output row n. lane == batch index b.
//   acc[b] = sum_k vals[n,k] * x_T[cols[n,k]][b]
// cols/vals staged in smem packed as int2 (single LDS.64 broadcast per k).
// Output staged through smem so the strided [B,N] store is sector-coalesced.
// ---------------------------------------------------------------------------
constexpr int WARPS_PER_BLOCK = 8;

__global__ __launch_bounds__(WARPS_PER_BLOCK * 32)
void gather_dot_kernel(const float* __restrict__ vals,
                       const int*   __restrict__ cols,
                       float*       __restrict__ out)
{
    __shared__ int2  s_cv[WARPS_PER_BLOCK][KDIM];   // (col, val bits)
    __shared__ float s_acc[WARPS_PER_BLOCK][33];    // [n_off][b], padded

    const int w    = threadIdx.x >> 5;
    const int lane = threadIdx.x & 31;
    const int n    = blockIdx.x * WARPS_PER_BLOCK + w;

    float acc = 0.0f;
    if (n < NDIM) {
        const int*   cptr = cols + (size_t)n * KDIM;
        const float* vptr = vals + (size_t)n * KDIM;

        // Stage this row's 288 (col,val) pairs into smem, coalesced.
        #pragma unroll
        for (int i = 0; i < KDIM / 32; ++i) {
            int   c = __ldg(cptr + i * 32 + lane);
            float v = __ldg(vptr + i * 32 + lane);
            int2 cv;
            cv.x = c;
            cv.y = __float_as_int(v);
            s_cv[w][i * 32 + lane] = cv;
        }
        __syncwarp();

        // Main gather loop: one 128B coalesced L2 line per k.
        #pragma unroll 8
        for (int k = 0; k < KDIM; ++k) {
            int2  cv = s_cv[w][k];                       // broadcast LDS.64
            float xv = __ldg(&g_xT[(size_t)cv.x * BDIM + lane]);
            acc = fmaf(__int_as_float(cv.y), xv, acc);
        }
    }

    // Stage results and write out[b][n] sector-coalesced:
    // thread t: b = t/8, j = t%8 -> 8 consecutive n per b = one 32B sector.
    s_acc[w][lane] = acc;
    __syncthreads();

    const int b  = threadIdx.x >> 3;
    const int j  = threadIdx.x & 7;
    const int nn = blockIdx.x * WARPS_PER_BLOCK + j;
    if (nn < NDIM)
        out[(size_t)b * NDIM + nn] = s_acc[j][b];
}

// ---------------------------------------------------------------------------
// kernel_launch: inputs per metadata order: x_affine (f32), vals (f32), cols (i32)
// ---------------------------------------------------------------------------
extern "C" void kernel_launch(void* const* d_in, const int* in_sizes, int n_in,
                              void* d_out, int out_size)
{
    const float* x    = (const float*)d_in[0];
    const float* vals = (const float*)d_in[1];
    const int*   cols = (const int*)  d_in[2];
    float*       out  = (float*)d_out;

    (void)in_sizes; (void)n_in; (void)out_size;

    // 1) Transpose x [B,N] -> x_T [N,B]
    {
        dim3 block(32, 32);
        dim3 grid((NDIM + 31) / 32);
        transpose_kernel<<<grid, block>>>(x);
    }

    // 2) Gathered dot product
    {
        int grid = (NDIM + WARPS_PER_BLOCK - 1) / WARPS_PER_BLOCK;  // 4097
        gather_dot_kernel<<<grid, WARPS_PER_BLOCK * 32>>>(vals, cols, out);
    }
}